// round 1
// baseline (speedup 1.0000x reference)
#include <cuda_runtime.h>

// TraitSimilarity: out = (1/465) * sum over pairs 1<=j<k<32 of
//   [ (Gt[j,k] - cs_j*cs_k/N) >= 0 ] * (1 - Gp[j,k]/max(pn_j*pn_k, 1e-8))
// where Gp = y_pred^T y_pred, Gt = y_true^T y_true, cs = colsum(y_true),
// pn_j = sqrt(Gp[j,j]).

#define NBLK 1024   // blocks in gram kernel
#define TPB  128    // 4 warps

// scratch: per block [Gp(1024) | Gt(1024) | colsum(32)] = 2080 floats
__device__ float g_scratch[NBLK * 2080];
__device__ float g_reduced[2080];

// ---------------- packed f32x2 helpers ----------------
__device__ __forceinline__ unsigned long long pack2(float lo, float hi) {
    unsigned long long r;
    asm("mov.b64 %0, {%1, %2};" : "=l"(r) : "f"(lo), "f"(hi));
    return r;
}
__device__ __forceinline__ void fma2(unsigned long long& d,
                                     unsigned long long a,
                                     unsigned long long b) {
    asm("fma.rn.f32x2 %0, %1, %2, %0;" : "+l"(d) : "l"(a), "l"(b));
}
__device__ __forceinline__ void add2(unsigned long long& d, unsigned long long a) {
    asm("add.rn.f32x2 %0, %0, %1;" : "+l"(d) : "l"(a));
}
__device__ __forceinline__ float2 unpack2(unsigned long long v) {
    float2 f;
    asm("mov.b64 {%0, %1}, %2;" : "=f"(f.x), "=f"(f.y) : "l"(v));
    return f;
}

// ---------------- main Gram accumulation ----------------
// Lane (jb in 0..7, kb in 0..3) accumulates C[4*jb + j][8*kb + kk] for j in 0..3,
// kk in 0..7 — acc[j*4+i] holds the f32x2 pair (kk=2i, kk=2i+1).
template <bool COLSUM>
__device__ __forceinline__ void gram_rows(const float* __restrict__ src,
                                          int row0, int row1, int jb, int kb,
                                          unsigned long long* __restrict__ acc,
                                          unsigned long long* __restrict__ cs) {
#pragma unroll 4
    for (int r = row0; r < row1; ++r) {
        const float4* rowp = (const float4*)(src + (size_t)r * 32);
        // a fragment: 4 consecutive floats at column 4*jb
        float4 av = rowp[jb];
        // b fragment: 8 consecutive floats at column 8*kb, loaded as packed pairs
        const ulonglong2* rowq = (const ulonglong2*)rowp;
        ulonglong2 qa = rowq[2 * kb];
        ulonglong2 qb = rowq[2 * kb + 1];
        unsigned long long b0 = qa.x, b1 = qa.y, b2 = qb.x, b3 = qb.y;

        unsigned long long a0 = pack2(av.x, av.x);
        unsigned long long a1 = pack2(av.y, av.y);
        unsigned long long a2 = pack2(av.z, av.z);
        unsigned long long a3 = pack2(av.w, av.w);

        fma2(acc[0],  a0, b0); fma2(acc[1],  a0, b1); fma2(acc[2],  a0, b2); fma2(acc[3],  a0, b3);
        fma2(acc[4],  a1, b0); fma2(acc[5],  a1, b1); fma2(acc[6],  a1, b2); fma2(acc[7],  a1, b3);
        fma2(acc[8],  a2, b0); fma2(acc[9],  a2, b1); fma2(acc[10], a2, b2); fma2(acc[11], a2, b3);
        fma2(acc[12], a3, b0); fma2(acc[13], a3, b1); fma2(acc[14], a3, b2); fma2(acc[15], a3, b3);

        if (COLSUM) {
            add2(cs[0], b0); add2(cs[1], b1); add2(cs[2], b2); add2(cs[3], b3);
        }
    }
}

__global__ void __launch_bounds__(TPB, 4)
gram_kernel(const float* __restrict__ yp, const float* __restrict__ yt, int N) {
    __shared__ float sm[4][1024];
    __shared__ float smcs[4][32];

    const int w    = threadIdx.x >> 5;
    const int lane = threadIdx.x & 31;
    const int jb   = lane >> 2;   // 0..7 -> j block of 4
    const int kb   = lane & 3;    // 0..3 -> k block of 8

    const int rpb  = N / NBLK;        // rows per block (1024)
    const int rpw  = rpb / 4;         // rows per warp (256)
    const int row0 = blockIdx.x * rpb + w * rpw;
    const int row1 = row0 + rpw;

    unsigned long long acc[16];
    unsigned long long cs[4];
    float* outb = &g_scratch[(size_t)blockIdx.x * 2080];

    // ---------- phase 1: Gp from y_pred ----------
#pragma unroll
    for (int i = 0; i < 16; ++i) acc[i] = 0ull;
    gram_rows<false>(yp, row0, row1, jb, kb, acc, cs);

#pragma unroll
    for (int j = 0; j < 4; ++j) {
        const int jj = jb * 4 + j;
#pragma unroll
        for (int i = 0; i < 4; ++i) {
            float2 f = unpack2(acc[j * 4 + i]);
            const int kk = kb * 8 + 2 * i;
            sm[w][jj * 32 + kk]     = f.x;
            sm[w][jj * 32 + kk + 1] = f.y;
        }
    }
    __syncthreads();
    for (int o = threadIdx.x; o < 1024; o += TPB)
        outb[o] = sm[0][o] + sm[1][o] + sm[2][o] + sm[3][o];
    __syncthreads();

    // ---------- phase 2: Gt + colsum from y_true ----------
#pragma unroll
    for (int i = 0; i < 16; ++i) acc[i] = 0ull;
#pragma unroll
    for (int i = 0; i < 4; ++i) cs[i] = 0ull;
    gram_rows<true>(yt, row0, row1, jb, kb, acc, cs);

#pragma unroll
    for (int j = 0; j < 4; ++j) {
        const int jj = jb * 4 + j;
#pragma unroll
        for (int i = 0; i < 4; ++i) {
            float2 f = unpack2(acc[j * 4 + i]);
            const int kk = kb * 8 + 2 * i;
            sm[w][jj * 32 + kk]     = f.x;
            sm[w][jj * 32 + kk + 1] = f.y;
        }
    }
    // colsum: lanes with jb==0 hold the warp's colsum for k = 8*kb..8*kb+7
    if (jb == 0) {
#pragma unroll
        for (int i = 0; i < 4; ++i) {
            float2 f = unpack2(cs[i]);
            smcs[w][kb * 8 + 2 * i]     = f.x;
            smcs[w][kb * 8 + 2 * i + 1] = f.y;
        }
    }
    __syncthreads();
    for (int o = threadIdx.x; o < 1024; o += TPB)
        outb[1024 + o] = sm[0][o] + sm[1][o] + sm[2][o] + sm[3][o];
    if (threadIdx.x < 32) {
        const int t = threadIdx.x;
        outb[2048 + t] = smcs[0][t] + smcs[1][t] + smcs[2][t] + smcs[3][t];
    }
}

// ---------------- cross-block reduction ----------------
// grid = 2080/16 = 130 blocks, 256 threads. Coalesced: 16 consecutive outputs
// per block, 16 b-strides per output, fixed reduction order (deterministic).
__global__ void reduce_kernel() {
    __shared__ float sm[256];
    const int ol = threadIdx.x & 15;
    const int b0 = threadIdx.x >> 4;
    const int o  = blockIdx.x * 16 + ol;

    float s = 0.0f;
    for (int b = b0; b < NBLK; b += 16)
        s += g_scratch[(size_t)b * 2080 + o];
    sm[threadIdx.x] = s;
    __syncthreads();
#pragma unroll
    for (int d = 8; d > 0; d >>= 1) {
        if (b0 < d) sm[b0 * 16 + ol] += sm[(b0 + d) * 16 + ol];
        __syncthreads();
    }
    if (threadIdx.x < 16)
        g_reduced[blockIdx.x * 16 + threadIdx.x] = sm[threadIdx.x];
}

// ---------------- finalize: one warp ----------------
__global__ void final_kernel(float* __restrict__ out, float invN) {
    __shared__ float pn[32], csm[32];
    const int lane = threadIdx.x;
    pn[lane]  = sqrtf(g_reduced[lane * 33]);       // sqrt(Gp[j][j])
    csm[lane] = g_reduced[2048 + lane];
    __syncwarp();

    float sum = 0.0f;
    for (int idx = lane; idx < 465; idx += 32) {   // pairs 1 <= j < k < 32
        int j = 1, rem = idx;
        while (rem >= 31 - j) { rem -= 31 - j; ++j; }
        const int k = j + 1 + rem;
        const float num  = g_reduced[1024 + j * 32 + k] - csm[j] * csm[k] * invN;
        const float cosv = g_reduced[j * 32 + k] / fmaxf(pn[j] * pn[k], 1e-8f);
        if (num >= 0.0f) sum += 1.0f - cosv;
    }
#pragma unroll
    for (int d = 16; d > 0; d >>= 1)
        sum += __shfl_down_sync(0xffffffffu, sum, d);
    if (lane == 0) out[0] = sum / 465.0f;
}

extern "C" void kernel_launch(void* const* d_in, const int* in_sizes, int n_in,
                              void* d_out, int out_size) {
    const float* yp = (const float*)d_in[0];   // y_pred [N, 32]
    const float* yt = (const float*)d_in[1];   // y_true [N, 32]
    const int N = in_sizes[0] / 32;

    gram_kernel<<<NBLK, TPB>>>(yp, yt, N);
    reduce_kernel<<<130, 256>>>();
    final_kernel<<<1, 32>>>((float*)d_out, 1.0f / (float)N);
}